// round 1
// baseline (speedup 1.0000x reference)
#include <cuda_runtime.h>

// ---------------------------------------------------------------------------
// CausalSelfAttentionWithBias: B=4, T=2048, C=1024, H=16, D=64, fp32
// Stage 1: qkv = x @ W_attn + b_attn  -> scatter to q/k/v [B,H,T,D] (+head bias,
//          q pre-scaled by 1/sqrt(D))
// Stage 2: causal flash attention -> y [B,T,C]
// Stage 3: out = y @ W_proj + b_proj
// ---------------------------------------------------------------------------

#define M1   8192
#define K1   1024
#define N1   3072
#define N2   1024
#define TT   2048
#define HH   16
#define DD   64

#define BM 128
#define BN 128
#define BK 8
#define TM 8
#define TN 8

// scratch (allocation-free: __device__ globals)
__device__ float g_q[4 * HH * TT * DD];
__device__ float g_k[4 * HH * TT * DD];
__device__ float g_v[4 * HH * TT * DD];
__device__ float g_y[4 * TT * 1024];

// ---------------------------------------------------------------------------
// Stage 1: QKV GEMM with fused bias + head-bias + q-scale, scatter epilogue
// ---------------------------------------------------------------------------
__global__ __launch_bounds__(256)
void gemm_qkv_kernel(const float* __restrict__ A,      // x [8192,1024]
                     const float* __restrict__ B,      // W_attn [1024,3072]
                     const float* __restrict__ b_attn, // [3072]
                     const float* __restrict__ bQ,     // [16*64]
                     const float* __restrict__ bK,
                     const float* __restrict__ bV)
{
    __shared__ float As[BK][BM];
    __shared__ float Bs[BK][BN];

    const int tid  = threadIdx.x;
    const int cRow = blockIdx.y;
    const int cCol = blockIdx.x;
    const int threadCol = tid % 16;
    const int threadRow = tid / 16;

    const float* Ab = A + cRow * BM * K1;
    const float* Bb = B + cCol * BN;

    const int innerRowA = tid / 2,  innerColA = tid % 2;   // A float4: [128][8]
    const int innerRowB = tid / 32, innerColB = tid % 32;  // B float4: [8][128]

    float acc[TM][TN] = {};
    float regM[TM], regN[TN];

    for (int kb = 0; kb < K1; kb += BK) {
        float4 a4 = *(const float4*)(Ab + innerRowA * K1 + kb + innerColA * 4);
        As[innerColA * 4 + 0][innerRowA] = a4.x;
        As[innerColA * 4 + 1][innerRowA] = a4.y;
        As[innerColA * 4 + 2][innerRowA] = a4.z;
        As[innerColA * 4 + 3][innerRowA] = a4.w;
        *(float4*)(&Bs[innerRowB][innerColB * 4]) =
            *(const float4*)(Bb + (kb + innerRowB) * N1 + innerColB * 4);
        __syncthreads();

        #pragma unroll
        for (int k = 0; k < BK; k++) {
            #pragma unroll
            for (int i = 0; i < TM; i++) regM[i] = As[k][threadRow * TM + i];
            #pragma unroll
            for (int j = 0; j < TN; j++) regN[j] = Bs[k][threadCol * TN + j];
            #pragma unroll
            for (int i = 0; i < TM; i++)
                #pragma unroll
                for (int j = 0; j < TN; j++)
                    acc[i][j] += regM[i] * regN[j];
        }
        __syncthreads();
    }

    // epilogue: scatter to q/k/v [B,H,T,D]
    const int col0  = cCol * BN + threadCol * TN;
    const int which = col0 >> 10;        // 0=q,1=k,2=v (128-col block never crosses)
    const int cc0   = col0 & 1023;
    const int h     = cc0 >> 6;
    const int d0    = cc0 & 63;          // 8 cols never cross a 64-boundary

    const float* hb = (which == 0 ? bQ : (which == 1 ? bK : bV)) + h * 64 + d0;
    float* dstBase  = (which == 0 ? g_q : (which == 1 ? g_k : g_v));
    const float scale = (which == 0) ? 0.125f : 1.0f;   // 1/sqrt(64)

    float bias[TN];
    #pragma unroll
    for (int j = 0; j < TN; j++) bias[j] = b_attn[col0 + j] + hb[j];

    #pragma unroll
    for (int i = 0; i < TM; i++) {
        const int m = cRow * BM + threadRow * TM + i;
        const int b = m >> 11, t = m & 2047;
        float* dst = dstBase + ((size_t)(b * HH + h) * TT + t) * DD + d0;
        #pragma unroll
        for (int j = 0; j < TN; j++)
            dst[j] = (acc[i][j] + bias[j]) * scale;
    }
}

// ---------------------------------------------------------------------------
// Stage 2: causal flash attention, 64x64 tiles, fp32
// block = 256 threads: 64 q-rows x 4 lanes; lane c owns k-cols/out-dims c*16..
// ---------------------------------------------------------------------------
__global__ __launch_bounds__(256)
void attn_kernel()
{
    __shared__ float Ks[64 * 64];
    __shared__ float Vs[64 * 64];

    const int tid = threadIdx.x;
    const int bh  = blockIdx.y;       // b*16 + h
    const int qt  = blockIdx.x;       // q tile index
    const int q0  = qt * 64;
    const int row = tid >> 2;
    const int c   = tid & 3;

    // Q row into registers (pre-scaled by 1/sqrt(D) in stage 1)
    float4 qr[16];
    const float4* qrow = (const float4*)(g_q + ((size_t)bh * TT + q0 + row) * DD);
    #pragma unroll
    for (int i = 0; i < 16; i++) qr[i] = qrow[i];

    float o[16];
    #pragma unroll
    for (int i = 0; i < 16; i++) o[i] = 0.f;
    float mval = -1e30f, l = 0.f;

    const float4* kbase = (const float4*)(g_k + (size_t)bh * TT * DD);
    const float4* vbase = (const float4*)(g_v + (size_t)bh * TT * DD);
    float4* Ks4 = (float4*)Ks;
    float4* Vs4 = (float4*)Vs;

    for (int tIdx = 0; tIdx <= qt; ++tIdx) {
        __syncthreads();
        const int kof = tIdx * 1024;  // float4 units: 64 rows * 16
        #pragma unroll
        for (int i = 0; i < 4; i++) {
            Ks4[tid + i * 256] = kbase[kof + tid + i * 256];
            Vs4[tid + i * 256] = vbase[kof + tid + i * 256];
        }
        __syncthreads();

        // scores: s[j] = q_row . k_{c*16+j}
        float s[16];
        #pragma unroll
        for (int j = 0; j < 16; j++) {
            const float4* krow = (const float4*)(Ks + (c * 16 + j) * 64);
            float a0 = 0.f, a1 = 0.f, a2 = 0.f, a3 = 0.f;
            #pragma unroll
            for (int d = 0; d < 16; d += 4) {
                float4 k0 = krow[d + 0], k1 = krow[d + 1], k2 = krow[d + 2], k3 = krow[d + 3];
                a0 += qr[d+0].x*k0.x + qr[d+0].y*k0.y + qr[d+0].z*k0.z + qr[d+0].w*k0.w;
                a1 += qr[d+1].x*k1.x + qr[d+1].y*k1.y + qr[d+1].z*k1.z + qr[d+1].w*k1.w;
                a2 += qr[d+2].x*k2.x + qr[d+2].y*k2.y + qr[d+2].z*k2.z + qr[d+2].w*k2.w;
                a3 += qr[d+3].x*k3.x + qr[d+3].y*k3.y + qr[d+3].z*k3.z + qr[d+3].w*k3.w;
            }
            s[j] = (a0 + a1) + (a2 + a3);
        }

        if (tIdx == qt) {   // diagonal tile: mask k > q
            #pragma unroll
            for (int j = 0; j < 16; j++)
                if (c * 16 + j > row) s[j] = -1e30f;
        }

        // online softmax (row = 4 lanes)
        float mt = s[0];
        #pragma unroll
        for (int j = 1; j < 16; j++) mt = fmaxf(mt, s[j]);
        mt = fmaxf(mt, __shfl_xor_sync(0xffffffffu, mt, 1));
        mt = fmaxf(mt, __shfl_xor_sync(0xffffffffu, mt, 2));
        const float mnew = fmaxf(mval, mt);
        const float corr = __expf(mval - mnew);
        float ls = 0.f;
        #pragma unroll
        for (int j = 0; j < 16; j++) { s[j] = __expf(s[j] - mnew); ls += s[j]; }
        ls += __shfl_xor_sync(0xffffffffu, ls, 1);
        ls += __shfl_xor_sync(0xffffffffu, ls, 2);
        l = l * corr + ls;
        mval = mnew;
        #pragma unroll
        for (int i = 0; i < 16; i++) o[i] *= corr;

        // PV: broadcast p within the 4-lane row group via shfl(width=4)
        #pragma unroll
        for (int jo = 0; jo < 4; jo++) {
            #pragma unroll
            for (int ji = 0; ji < 16; ji++) {
                const float p = __shfl_sync(0xffffffffu, s[ji], jo, 4);
                const float4* vr = (const float4*)(Vs + (jo * 16 + ji) * 64 + c * 16);
                float4 a0 = vr[0], a1 = vr[1], a2 = vr[2], a3 = vr[3];
                o[0]  += p * a0.x; o[1]  += p * a0.y; o[2]  += p * a0.z; o[3]  += p * a0.w;
                o[4]  += p * a1.x; o[5]  += p * a1.y; o[6]  += p * a1.z; o[7]  += p * a1.w;
                o[8]  += p * a2.x; o[9]  += p * a2.y; o[10] += p * a2.z; o[11] += p * a2.w;
                o[12] += p * a3.x; o[13] += p * a3.y; o[14] += p * a3.z; o[15] += p * a3.w;
            }
        }
    }

    const float inv = 1.f / l;
    const int b = bh >> 4, h = bh & 15;
    float4* yp = (float4*)(g_y + ((size_t)(b * TT) + q0 + row) * 1024 + h * 64 + c * 16);
    #pragma unroll
    for (int i = 0; i < 4; i++) {
        float4 w;
        w.x = o[i*4+0] * inv; w.y = o[i*4+1] * inv;
        w.z = o[i*4+2] * inv; w.w = o[i*4+3] * inv;
        yp[i] = w;
    }
}

// ---------------------------------------------------------------------------
// Stage 3: output projection GEMM + bias
// ---------------------------------------------------------------------------
__global__ __launch_bounds__(256)
void gemm_proj_kernel(const float* __restrict__ B,      // W_proj [1024,1024]
                      const float* __restrict__ b_proj, // [1024]
                      float* __restrict__ out)          // [8192,1024]
{
    __shared__ float As[BK][BM];
    __shared__ float Bs[BK][BN];

    const int tid  = threadIdx.x;
    const int cRow = blockIdx.y;
    const int cCol = blockIdx.x;
    const int threadCol = tid % 16;
    const int threadRow = tid / 16;

    const float* Ab = g_y + cRow * BM * N2;
    const float* Bb = B + cCol * BN;

    const int innerRowA = tid / 2,  innerColA = tid % 2;
    const int innerRowB = tid / 32, innerColB = tid % 32;

    float acc[TM][TN] = {};
    float regM[TM], regN[TN];

    for (int kb = 0; kb < N2; kb += BK) {
        float4 a4 = *(const float4*)(Ab + innerRowA * N2 + kb + innerColA * 4);
        As[innerColA * 4 + 0][innerRowA] = a4.x;
        As[innerColA * 4 + 1][innerRowA] = a4.y;
        As[innerColA * 4 + 2][innerRowA] = a4.z;
        As[innerColA * 4 + 3][innerRowA] = a4.w;
        *(float4*)(&Bs[innerRowB][innerColB * 4]) =
            *(const float4*)(Bb + (kb + innerRowB) * N2 + innerColB * 4);
        __syncthreads();

        #pragma unroll
        for (int k = 0; k < BK; k++) {
            #pragma unroll
            for (int i = 0; i < TM; i++) regM[i] = As[k][threadRow * TM + i];
            #pragma unroll
            for (int j = 0; j < TN; j++) regN[j] = Bs[k][threadCol * TN + j];
            #pragma unroll
            for (int i = 0; i < TM; i++)
                #pragma unroll
                for (int j = 0; j < TN; j++)
                    acc[i][j] += regM[i] * regN[j];
        }
        __syncthreads();
    }

    const int col0 = cCol * BN + threadCol * TN;
    float bias[TN];
    #pragma unroll
    for (int j = 0; j < TN; j++) bias[j] = b_proj[col0 + j];

    #pragma unroll
    for (int i = 0; i < TM; i++) {
        const int m = cRow * BM + threadRow * TM + i;
        float* dst = out + (size_t)m * N2 + col0;
        #pragma unroll
        for (int j = 0; j < TN; j++)
            dst[j] = acc[i][j] + bias[j];
    }
}

// ---------------------------------------------------------------------------
extern "C" void kernel_launch(void* const* d_in, const int* in_sizes, int n_in,
                              void* d_out, int out_size)
{
    (void)in_sizes; (void)n_in; (void)out_size;
    const float* x      = (const float*)d_in[0];
    const float* W_attn = (const float*)d_in[1];
    const float* b_attn = (const float*)d_in[2];
    const float* W_proj = (const float*)d_in[3];
    const float* b_proj = (const float*)d_in[4];
    const float* bQ     = (const float*)d_in[5];
    const float* bK     = (const float*)d_in[6];
    const float* bV     = (const float*)d_in[7];
    float* out = (float*)d_out;

    dim3 g1(N1 / BN, M1 / BM);   // (24, 64)
    gemm_qkv_kernel<<<g1, 256>>>(x, W_attn, b_attn, bQ, bK, bV);

    dim3 ga(TT / 64, 4 * HH);    // (32, 64)
    attn_kernel<<<ga, 256>>>();

    dim3 g2(N2 / BN, M1 / BM);   // (8, 64)
    gemm_proj_kernel<<<g2, 256>>>(W_proj, b_proj, out);
}

// round 2
// speedup vs baseline: 1.0003x; 1.0003x over previous
#include <cuda_runtime.h>

// ---------------------------------------------------------------------------
// CausalSelfAttentionWithBias: B=4, T=2048, C=1024, H=16, D=64, fp32
// Stage 1: qkv = x @ W_attn + b_attn  -> scatter to q/k/v [B,H,T,D] (+head bias,
//          q pre-scaled by 1/sqrt(D))
// Stage 2: causal flash attention -> y [B,T,C]
// Stage 3: out = y @ W_proj + b_proj
// ---------------------------------------------------------------------------

#define M1   8192
#define K1   1024
#define N1   3072
#define N2   1024
#define TT   2048
#define HH   16
#define DD   64

#define BM 128
#define BN 128
#define BK 8
#define TM 8
#define TN 8

// scratch (allocation-free: __device__ globals)
__device__ float g_q[4 * HH * TT * DD];
__device__ float g_k[4 * HH * TT * DD];
__device__ float g_v[4 * HH * TT * DD];
__device__ float g_y[4 * TT * 1024];

// ---------------------------------------------------------------------------
// Stage 1: QKV GEMM with fused bias + head-bias + q-scale, scatter epilogue
// ---------------------------------------------------------------------------
__global__ __launch_bounds__(256)
void gemm_qkv_kernel(const float* __restrict__ A,      // x [8192,1024]
                     const float* __restrict__ B,      // W_attn [1024,3072]
                     const float* __restrict__ b_attn, // [3072]
                     const float* __restrict__ bQ,     // [16*64]
                     const float* __restrict__ bK,
                     const float* __restrict__ bV)
{
    __shared__ float As[BK][BM];
    __shared__ float Bs[BK][BN];

    const int tid  = threadIdx.x;
    const int cRow = blockIdx.y;
    const int cCol = blockIdx.x;
    const int threadCol = tid % 16;
    const int threadRow = tid / 16;

    const float* Ab = A + cRow * BM * K1;
    const float* Bb = B + cCol * BN;

    const int innerRowA = tid / 2,  innerColA = tid % 2;   // A float4: [128][8]
    const int innerRowB = tid / 32, innerColB = tid % 32;  // B float4: [8][128]

    float acc[TM][TN] = {};
    float regM[TM], regN[TN];

    for (int kb = 0; kb < K1; kb += BK) {
        float4 a4 = *(const float4*)(Ab + innerRowA * K1 + kb + innerColA * 4);
        As[innerColA * 4 + 0][innerRowA] = a4.x;
        As[innerColA * 4 + 1][innerRowA] = a4.y;
        As[innerColA * 4 + 2][innerRowA] = a4.z;
        As[innerColA * 4 + 3][innerRowA] = a4.w;
        *(float4*)(&Bs[innerRowB][innerColB * 4]) =
            *(const float4*)(Bb + (kb + innerRowB) * N1 + innerColB * 4);
        __syncthreads();

        #pragma unroll
        for (int k = 0; k < BK; k++) {
            #pragma unroll
            for (int i = 0; i < TM; i++) regM[i] = As[k][threadRow * TM + i];
            #pragma unroll
            for (int j = 0; j < TN; j++) regN[j] = Bs[k][threadCol * TN + j];
            #pragma unroll
            for (int i = 0; i < TM; i++)
                #pragma unroll
                for (int j = 0; j < TN; j++)
                    acc[i][j] += regM[i] * regN[j];
        }
        __syncthreads();
    }

    // epilogue: scatter to q/k/v [B,H,T,D]
    const int col0  = cCol * BN + threadCol * TN;
    const int which = col0 >> 10;        // 0=q,1=k,2=v (128-col block never crosses)
    const int cc0   = col0 & 1023;
    const int h     = cc0 >> 6;
    const int d0    = cc0 & 63;          // 8 cols never cross a 64-boundary

    const float* hb = (which == 0 ? bQ : (which == 1 ? bK : bV)) + h * 64 + d0;
    float* dstBase  = (which == 0 ? g_q : (which == 1 ? g_k : g_v));
    const float scale = (which == 0) ? 0.125f : 1.0f;   // 1/sqrt(64)

    float bias[TN];
    #pragma unroll
    for (int j = 0; j < TN; j++) bias[j] = b_attn[col0 + j] + hb[j];

    #pragma unroll
    for (int i = 0; i < TM; i++) {
        const int m = cRow * BM + threadRow * TM + i;
        const int b = m >> 11, t = m & 2047;
        float* dst = dstBase + ((size_t)(b * HH + h) * TT + t) * DD + d0;
        #pragma unroll
        for (int j = 0; j < TN; j++)
            dst[j] = (acc[i][j] + bias[j]) * scale;
    }
}

// ---------------------------------------------------------------------------
// Stage 2: causal flash attention, 64x64 tiles, fp32
// block = 256 threads: 64 q-rows x 4 lanes; lane c owns k-cols/out-dims c*16..
// ---------------------------------------------------------------------------
__global__ __launch_bounds__(256)
void attn_kernel()
{
    __shared__ float Ks[64 * 64];
    __shared__ float Vs[64 * 64];

    const int tid = threadIdx.x;
    const int bh  = blockIdx.y;       // b*16 + h
    const int qt  = blockIdx.x;       // q tile index
    const int q0  = qt * 64;
    const int row = tid >> 2;
    const int c   = tid & 3;

    // Q row into registers (pre-scaled by 1/sqrt(D) in stage 1)
    float4 qr[16];
    const float4* qrow = (const float4*)(g_q + ((size_t)bh * TT + q0 + row) * DD);
    #pragma unroll
    for (int i = 0; i < 16; i++) qr[i] = qrow[i];

    float o[16];
    #pragma unroll
    for (int i = 0; i < 16; i++) o[i] = 0.f;
    float mval = -1e30f, l = 0.f;

    const float4* kbase = (const float4*)(g_k + (size_t)bh * TT * DD);
    const float4* vbase = (const float4*)(g_v + (size_t)bh * TT * DD);
    float4* Ks4 = (float4*)Ks;
    float4* Vs4 = (float4*)Vs;

    for (int tIdx = 0; tIdx <= qt; ++tIdx) {
        __syncthreads();
        const int kof = tIdx * 1024;  // float4 units: 64 rows * 16
        #pragma unroll
        for (int i = 0; i < 4; i++) {
            Ks4[tid + i * 256] = kbase[kof + tid + i * 256];
            Vs4[tid + i * 256] = vbase[kof + tid + i * 256];
        }
        __syncthreads();

        // scores: s[j] = q_row . k_{c*16+j}
        float s[16];
        #pragma unroll
        for (int j = 0; j < 16; j++) {
            const float4* krow = (const float4*)(Ks + (c * 16 + j) * 64);
            float a0 = 0.f, a1 = 0.f, a2 = 0.f, a3 = 0.f;
            #pragma unroll
            for (int d = 0; d < 16; d += 4) {
                float4 k0 = krow[d + 0], k1 = krow[d + 1], k2 = krow[d + 2], k3 = krow[d + 3];
                a0 += qr[d+0].x*k0.x + qr[d+0].y*k0.y + qr[d+0].z*k0.z + qr[d+0].w*k0.w;
                a1 += qr[d+1].x*k1.x + qr[d+1].y*k1.y + qr[d+1].z*k1.z + qr[d+1].w*k1.w;
                a2 += qr[d+2].x*k2.x + qr[d+2].y*k2.y + qr[d+2].z*k2.z + qr[d+2].w*k2.w;
                a3 += qr[d+3].x*k3.x + qr[d+3].y*k3.y + qr[d+3].z*k3.z + qr[d+3].w*k3.w;
            }
            s[j] = (a0 + a1) + (a2 + a3);
        }

        if (tIdx == qt) {   // diagonal tile: mask k > q
            #pragma unroll
            for (int j = 0; j < 16; j++)
                if (c * 16 + j > row) s[j] = -1e30f;
        }

        // online softmax (row = 4 lanes)
        float mt = s[0];
        #pragma unroll
        for (int j = 1; j < 16; j++) mt = fmaxf(mt, s[j]);
        mt = fmaxf(mt, __shfl_xor_sync(0xffffffffu, mt, 1));
        mt = fmaxf(mt, __shfl_xor_sync(0xffffffffu, mt, 2));
        const float mnew = fmaxf(mval, mt);
        const float corr = __expf(mval - mnew);
        float ls = 0.f;
        #pragma unroll
        for (int j = 0; j < 16; j++) { s[j] = __expf(s[j] - mnew); ls += s[j]; }
        ls += __shfl_xor_sync(0xffffffffu, ls, 1);
        ls += __shfl_xor_sync(0xffffffffu, ls, 2);
        l = l * corr + ls;
        mval = mnew;
        #pragma unroll
        for (int i = 0; i < 16; i++) o[i] *= corr;

        // PV: broadcast p within the 4-lane row group via shfl(width=4)
        #pragma unroll
        for (int jo = 0; jo < 4; jo++) {
            #pragma unroll
            for (int ji = 0; ji < 16; ji++) {
                const float p = __shfl_sync(0xffffffffu, s[ji], jo, 4);
                const float4* vr = (const float4*)(Vs + (jo * 16 + ji) * 64 + c * 16);
                float4 a0 = vr[0], a1 = vr[1], a2 = vr[2], a3 = vr[3];
                o[0]  += p * a0.x; o[1]  += p * a0.y; o[2]  += p * a0.z; o[3]  += p * a0.w;
                o[4]  += p * a1.x; o[5]  += p * a1.y; o[6]  += p * a1.z; o[7]  += p * a1.w;
                o[8]  += p * a2.x; o[9]  += p * a2.y; o[10] += p * a2.z; o[11] += p * a2.w;
                o[12] += p * a3.x; o[13] += p * a3.y; o[14] += p * a3.z; o[15] += p * a3.w;
            }
        }
    }

    const float inv = 1.f / l;
    const int b = bh >> 4, h = bh & 15;
    float4* yp = (float4*)(g_y + ((size_t)(b * TT) + q0 + row) * 1024 + h * 64 + c * 16);
    #pragma unroll
    for (int i = 0; i < 4; i++) {
        float4 w;
        w.x = o[i*4+0] * inv; w.y = o[i*4+1] * inv;
        w.z = o[i*4+2] * inv; w.w = o[i*4+3] * inv;
        yp[i] = w;
    }
}

// ---------------------------------------------------------------------------
// Stage 3: output projection GEMM + bias
// ---------------------------------------------------------------------------
__global__ __launch_bounds__(256)
void gemm_proj_kernel(const float* __restrict__ B,      // W_proj [1024,1024]
                      const float* __restrict__ b_proj, // [1024]
                      float* __restrict__ out)          // [8192,1024]
{
    __shared__ float As[BK][BM];
    __shared__ float Bs[BK][BN];

    const int tid  = threadIdx.x;
    const int cRow = blockIdx.y;
    const int cCol = blockIdx.x;
    const int threadCol = tid % 16;
    const int threadRow = tid / 16;

    const float* Ab = g_y + cRow * BM * N2;
    const float* Bb = B + cCol * BN;

    const int innerRowA = tid / 2,  innerColA = tid % 2;
    const int innerRowB = tid / 32, innerColB = tid % 32;

    float acc[TM][TN] = {};
    float regM[TM], regN[TN];

    for (int kb = 0; kb < N2; kb += BK) {
        float4 a4 = *(const float4*)(Ab + innerRowA * N2 + kb + innerColA * 4);
        As[innerColA * 4 + 0][innerRowA] = a4.x;
        As[innerColA * 4 + 1][innerRowA] = a4.y;
        As[innerColA * 4 + 2][innerRowA] = a4.z;
        As[innerColA * 4 + 3][innerRowA] = a4.w;
        *(float4*)(&Bs[innerRowB][innerColB * 4]) =
            *(const float4*)(Bb + (kb + innerRowB) * N2 + innerColB * 4);
        __syncthreads();

        #pragma unroll
        for (int k = 0; k < BK; k++) {
            #pragma unroll
            for (int i = 0; i < TM; i++) regM[i] = As[k][threadRow * TM + i];
            #pragma unroll
            for (int j = 0; j < TN; j++) regN[j] = Bs[k][threadCol * TN + j];
            #pragma unroll
            for (int i = 0; i < TM; i++)
                #pragma unroll
                for (int j = 0; j < TN; j++)
                    acc[i][j] += regM[i] * regN[j];
        }
        __syncthreads();
    }

    const int col0 = cCol * BN + threadCol * TN;
    float bias[TN];
    #pragma unroll
    for (int j = 0; j < TN; j++) bias[j] = b_proj[col0 + j];

    #pragma unroll
    for (int i = 0; i < TM; i++) {
        const int m = cRow * BM + threadRow * TM + i;
        float* dst = out + (size_t)m * N2 + col0;
        #pragma unroll
        for (int j = 0; j < TN; j++)
            dst[j] = acc[i][j] + bias[j];
    }
}

// ---------------------------------------------------------------------------
extern "C" void kernel_launch(void* const* d_in, const int* in_sizes, int n_in,
                              void* d_out, int out_size)
{
    (void)in_sizes; (void)n_in; (void)out_size;
    const float* x      = (const float*)d_in[0];
    const float* W_attn = (const float*)d_in[1];
    const float* b_attn = (const float*)d_in[2];
    const float* W_proj = (const float*)d_in[3];
    const float* b_proj = (const float*)d_in[4];
    const float* bQ     = (const float*)d_in[5];
    const float* bK     = (const float*)d_in[6];
    const float* bV     = (const float*)d_in[7];
    float* out = (float*)d_out;

    dim3 g1(N1 / BN, M1 / BM);   // (24, 64)
    gemm_qkv_kernel<<<g1, 256>>>(x, W_attn, b_attn, bQ, bK, bV);

    dim3 ga(TT / 64, 4 * HH);    // (32, 64)
    attn_kernel<<<ga, 256>>>();

    dim3 g2(N2 / BN, M1 / BM);   // (8, 64)
    gemm_proj_kernel<<<g2, 256>>>(W_proj, b_proj, out);
}